// round 6
// baseline (speedup 1.0000x reference)
#include <cuda_runtime.h>

#define B 32
#define U 512
#define C 4096
#define DK 32
#define DV 32
#define UC (U*C)
#define MEM_RATE 0.01f
#define RWD_RATE 0.01f

// output layout: outputs[B,U,DV] | w[B,U,C] | key_new[U,C,DK] | value_new[U,C,DV] | reward_new[U,C]
#define OUT_W    524288
#define OUT_KEY  67633152
#define OUT_VAL  134742016
#define OUT_RWD  201850880

typedef unsigned long long u64;

__device__ __forceinline__ u64 pack2(float lo, float hi){
    u64 r; asm("mov.b64 %0, {%1,%2};" : "=l"(r) : "f"(lo), "f"(hi)); return r;
}
__device__ __forceinline__ void unpack2(u64 v, float& lo, float& hi){
    asm("mov.b64 {%0,%1}, %2;" : "=f"(lo), "=f"(hi) : "l"(v));
}
__device__ __forceinline__ void fma2(u64& d, u64 a, u64 b_){
    asm("fma.rn.f32x2 %0, %1, %2, %0;" : "+l"(d) : "l"(a), "l"(b_));
}
__device__ __forceinline__ void add2(u64& d, u64 a){
    asm("add.rn.f32x2 %0, %0, %1;" : "+l"(d) : "l"(a));
}

// scratch (static __device__ per harness rules)
__device__ float g_q_kb[U*DK*B];     // [u][k][b], pre-scaled by 1/temperature[u]  (for K1)
__device__ float g_q_bk[U*B*DK];     // [u][b][k], unscaled                        (for K2 refresh)
__device__ float g_denpart[U*4*B];   // per-(u,quarter) partial denominators
__device__ float g_opart[U*8*B*DV];  // per-(u,octant) output partials [B][DV]
__device__ int   g_mask_mode;        // 0 = uint8, 1 = float32, 2 = int32

// ---------------------------------------------------------------------------
// K_detect: sniff the mask dtype from its bit patterns (1 warp).
// ---------------------------------------------------------------------------
__global__ void k_detect(const unsigned int* __restrict__ m)
{
    int t = threadIdx.x;
    int f32 = 0, big = 0;
    for (int i = t; i < 2048; i += 32){
        unsigned int v = m[i];
        f32 |= (v == 0x3F800000u);
        big |= (v > 1u && v != 0x3F800000u);
    }
    f32 = __any_sync(0xffffffffu, f32);
    big = __any_sync(0xffffffffu, big);
    if (t == 0) g_mask_mode = f32 ? 1 : (big ? 0 : 2);
}

// ---------------------------------------------------------------------------
// K0: query[b,u,k] = sum_d attention[b,u,d] * W_att[u,d,k]
// ---------------------------------------------------------------------------
__global__ __launch_bounds__(256) void k0_query(const float* __restrict__ att,
                                                const float* __restrict__ Watt,
                                                const float* __restrict__ temp)
{
    __shared__ float W_s[DK][DK];
    __shared__ float a_s[B][DK+1];
    const int u = blockIdx.x, t = threadIdx.x;

    for (int j = t; j < DK*DK; j += 256) W_s[j/DK][j%DK] = Watt[u*DK*DK + j];
    for (int j = t; j < B*DK; j += 256){
        int b = j/DK, d = j%DK;
        a_s[b][d] = att[(b*U + u)*DK + d];
    }
    __syncthreads();
    const float invT = 1.0f / temp[u];
    for (int j = t; j < B*DK; j += 256){
        int b = j/DK, k = j%DK;
        float s = 0.f;
        #pragma unroll
        for (int d = 0; d < DK; d++) s += a_s[b][d] * W_s[d][k];
        g_q_bk[u*B*DK + b*DK + k] = s;
        g_q_kb[u*DK*B + k*B + b] = s * invT;
    }
}

// ---------------------------------------------------------------------------
// K1: per (u, quarter-of-C): n[b,c] = exp(key.q)*rmem*mask -> w region;
//     partial per-b denominators -> g_denpart
// ---------------------------------------------------------------------------
__global__ __launch_bounds__(256) void k1_logits(const float* __restrict__ key_mem,
                                                 const void* __restrict__ mask,
                                                 const float* __restrict__ rmem,
                                                 float* __restrict__ w_out)   // base of w region
{
    const int u  = blockIdx.x >> 2;
    const int q4 = blockIdx.x & 3;
    const int t  = threadIdx.x;
    __shared__ __align__(16) float q_s[DK*B];        // [k][b], scaled
    __shared__ float key_s[DK*257 + 32];             // key tile transposed [k][c]; reused for reduction
    __shared__ float p2[B][8];

    for (int j = t; j < DK*B; j += 256) q_s[j] = g_q_kb[u*DK*B + j];

    const int mode = g_mask_mode;
    const unsigned char* __restrict__ mp8 = (const unsigned char*)mask + (size_t)u*C;
    const float*         __restrict__ mpf = (const float*)mask         + (size_t)u*C;
    const int*           __restrict__ mpi = (const int*)mask           + (size_t)u*C;

    const float* __restrict__ rmemu = rmem + u*C;
    float* __restrict__ nbase = w_out + u*C;

    u64 dpart2[16];
    #pragma unroll
    for (int i = 0; i < 16; i++) dpart2[i] = 0ull;

    for (int tile = q4*4; tile < q4*4 + 4; ++tile){
        const int c0 = tile * 256;
        __syncthreads();
        // stage key tile [256 c][32 k] transposed into key_s[k][c] (conflict-free)
        {
            const float4* __restrict__ gk =
                (const float4*)(key_mem + (size_t)u*C*DK + (size_t)c0*DK);
            #pragma unroll
            for (int j = 0; j < 8; j++){
                int f = t + j*256;
                float4 v = gk[f];
                int c = f >> 3, db = (f & 7) * 4;
                key_s[(db+0)*257 + c] = v.x;
                key_s[(db+1)*257 + c] = v.y;
                key_s[(db+2)*257 + c] = v.z;
                key_s[(db+3)*257 + c] = v.w;
            }
        }
        __syncthreads();

        const int c = c0 + t;
        u64 acc2[16];
        #pragma unroll
        for (int i = 0; i < 16; i++) acc2[i] = 0ull;

        #pragma unroll 8
        for (int k = 0; k < DK; k++){
            float kd = key_s[k*257 + t];
            u64 kd2 = pack2(kd, kd);
            const ulonglong2* __restrict__ qp = (const ulonglong2*)(&q_s[k*B]);
            #pragma unroll
            for (int j = 0; j < 8; j++){
                ulonglong2 p = qp[j];
                fma2(acc2[2*j],   kd2, p.x);
                fma2(acc2[2*j+1], kd2, p.y);
            }
        }

        const float rm = rmemu[c];
        float* __restrict__ np = nbase + c;
        #pragma unroll
        for (int i = 0; i < 16; i++){
            float l0, l1; unpack2(acc2[i], l0, l1);
            float e0 = __expf(l0) * rm;
            float e1 = __expf(l1) * rm;
            int b0 = 2*i, b1 = 2*i + 1;
            size_t i0 = (size_t)b0*UC + c;
            size_t i1 = (size_t)b1*UC + c;
            bool keep0, keep1;
            if (mode == 0)      { keep0 = mp8[i0] != 0;   keep1 = mp8[i1] != 0;   }
            else if (mode == 1) { keep0 = mpf[i0] != 0.f; keep1 = mpf[i1] != 0.f; }
            else                { keep0 = mpi[i0] != 0;   keep1 = mpi[i1] != 0;   }
            float n0 = keep0 ? e0 : 0.f;
            float n1 = keep1 ? e1 : 0.f;
            np[(size_t)b0*UC] = n0;
            np[(size_t)b1*UC] = n1;
            add2(dpart2[i], pack2(n0, n1));
        }
    }

    // deterministic partial-denominator reduction (reuse key_s as [b][256] scratch)
    __syncthreads();
    #pragma unroll
    for (int i = 0; i < 16; i++){
        float d0, d1; unpack2(dpart2[i], d0, d1);
        key_s[(2*i)*256 + t]   = d0;
        key_s[(2*i+1)*256 + t] = d1;
    }
    __syncthreads();
    {
        int b = t >> 3, seg = t & 7;
        float s = 0.f;
        #pragma unroll
        for (int j = 0; j < 32; j++) s += key_s[b*256 + seg*32 + j];
        p2[b][seg] = s;
    }
    __syncthreads();
    if (t < B){
        float s = 0.f;
        #pragma unroll
        for (int j = 0; j < 8; j++) s += p2[t][j];
        g_denpart[(u*4 + q4)*B + t] = s;
    }
}

// ---------------------------------------------------------------------------
// K2: per (u, octant-of-C): invden from partials, finalize w, retain,
//     key/value/reward refresh, partial outputs -> g_opart
// ---------------------------------------------------------------------------
__global__ __launch_bounds__(256) void k2_finalize(const float* __restrict__ valin,
                                                   const float* __restrict__ reward,
                                                   const float* __restrict__ key_mem,
                                                   const float* __restrict__ value_mem,
                                                   const float* __restrict__ rmem,
                                                   float* __restrict__ out)
{
    const int u   = blockIdx.x >> 3;
    const int oct = blockIdx.x & 7;
    const int t   = threadIdx.x;
    __shared__ __align__(16) float w_s[B][128];
    __shared__ __align__(16) float vm_s[128][DV];
    __shared__ __align__(16) float q_s[B][DK];
    __shared__ __align__(16) float v_s[B][DV];
    __shared__ float S_s[128];
    __shared__ float Spart[2][128];
    __shared__ float invden_s[B], rw_s[B];

    for (int j = t; j < B*DK; j += 256) q_s[j/DK][j%DK] = g_q_bk[u*B*DK + j];
    for (int j = t; j < B*DV; j += 256){
        int b = j/DV, v = j%DV;
        v_s[b][v] = valin[(b*U + u)*DV + v];
    }
    if (t < B){
        const float* dp = g_denpart + (size_t)(u*4)*B + t;
        invden_s[t] = 1.0f / (dp[0] + dp[B] + dp[2*B] + dp[3*B]);
        rw_s[t] = reward[t];
    }

    float* __restrict__ w_out   = out + OUT_W   + (size_t)u*C;
    float* __restrict__ key_out = out + OUT_KEY + (size_t)u*C*DK;
    float* __restrict__ val_out = out + OUT_VAL + (size_t)u*C*DV;
    float* __restrict__ rwd_out = out + OUT_RWD + (size_t)u*C;
    const float* __restrict__ km    = key_mem   + (size_t)u*C*DK;
    const float* __restrict__ vm    = value_mem + (size_t)u*C*DV;
    const float* __restrict__ rmemu = rmem      + (size_t)u*C;

    const int b_o = t >> 3;     // outputs accumulator: batch row
    const int vg  = t & 7;      // outputs accumulator: 4-wide v group
    u64 oacc0 = 0ull, oacc1 = 0ull;

    __syncthreads();

    for (int tile = oct*4; tile < oct*4 + 4; ++tile){
        const int c0 = tile * 128;

        // Phase A: finalize w, stage w_s, column sums
        {
            int half = t >> 7;
            int c = t & 127;
            float sacc = 0.f;
            #pragma unroll
            for (int j = 0; j < 16; j++){
                int b = half*16 + j;
                int gi = b*UC + c0 + c;
                float n = w_out[gi];
                float w = n * invden_s[b];
                w_out[gi] = w;
                w_s[b][c] = w;
                sacc += w;
            }
            Spart[half][c] = sacc;
        }
        __syncthreads();
        if (t < 128) S_s[t] = Spart[0][t] + Spart[1][t];
        // stage value_mem tile (contiguous 16KB)
        {
            const float4* __restrict__ src = (const float4*)(vm + (size_t)c0*DV);
            float4* __restrict__ dst = (float4*)(&vm_s[0][0]);
            #pragma unroll
            for (int j = 0; j < 4; j++) dst[t + j*256] = src[t + j*256];
        }
        __syncthreads();

        // Phase B: key/value refresh GEMMs  [128c x 32k], K = 32 batches
        {
            const int kg = t & 7;       // k = kg*4 .. +3
            const int cg = t >> 3;      // c_local = cg*4 .. +3
            u64 kacc[4][2], vacc[4][2];
            #pragma unroll
            for (int i = 0; i < 4; i++){
                kacc[i][0]=0ull; kacc[i][1]=0ull; vacc[i][0]=0ull; vacc[i][1]=0ull;
            }
            #pragma unroll 8
            for (int b = 0; b < B; b++){
                float4 w4 = *(const float4*)(&w_s[b][cg*4]);
                ulonglong2 q2 = *(const ulonglong2*)(&q_s[b][kg*4]);
                ulonglong2 v2 = *(const ulonglong2*)(&v_s[b][kg*4]);
                float wa[4] = {w4.x, w4.y, w4.z, w4.w};
                #pragma unroll
                for (int i = 0; i < 4; i++){
                    u64 wp = pack2(wa[i], wa[i]);
                    fma2(kacc[i][0], wp, q2.x);
                    fma2(kacc[i][1], wp, q2.y);
                    fma2(vacc[i][0], wp, v2.x);
                    fma2(vacc[i][1], wp, v2.y);
                }
            }
            #pragma unroll
            for (int i = 0; i < 4; i++){
                int cl = cg*4 + i;
                int c  = c0 + cl;
                float retain = 1.0f - MEM_RATE * S_s[cl];
                float a0,a1,a2,a3;
                unpack2(kacc[i][0], a0, a1); unpack2(kacc[i][1], a2, a3);
                float4 kmv = *(const float4*)(km + (size_t)c*DK + kg*4);
                float4 r;
                r.x = kmv.x*retain + MEM_RATE*a0;
                r.y = kmv.y*retain + MEM_RATE*a1;
                r.z = kmv.z*retain + MEM_RATE*a2;
                r.w = kmv.w*retain + MEM_RATE*a3;
                *(float4*)(key_out + (size_t)c*DK + kg*4) = r;

                unpack2(vacc[i][0], a0, a1); unpack2(vacc[i][1], a2, a3);
                float4 vmv = *(const float4*)(&vm_s[cl][kg*4]);
                float4 r2;
                r2.x = vmv.x*retain + MEM_RATE*a0;
                r2.y = vmv.y*retain + MEM_RATE*a1;
                r2.z = vmv.z*retain + MEM_RATE*a2;
                r2.w = vmv.w*retain + MEM_RATE*a3;
                *(float4*)(val_out + (size_t)c*DV + kg*4) = r2;
            }
        }

        // reward refresh
        if (t < 128){
            int c = t;
            float racc = 0.f;
            #pragma unroll
            for (int b = 0; b < B; b++) racc += w_s[b][c] * rw_s[b];
            float retain = 1.0f - RWD_RATE * S_s[c];
            rwd_out[c0 + c] = rmemu[c0 + c] * retain + RWD_RATE * racc;
        }

        // Phase C: outputs accumulation  o[b][v] += sum_c w[b][c]*value_mem[c][v]
        {
            #pragma unroll 8
            for (int c = 0; c < 128; c++){
                float w = w_s[b_o][c];
                u64 wp = pack2(w, w);
                ulonglong2 vv = *(const ulonglong2*)(&vm_s[c][vg*4]);
                fma2(oacc0, wp, vv.x);
                fma2(oacc1, wp, vv.y);
            }
        }
        __syncthreads();
    }

    // write output partials [CTA][B][DV]
    {
        float o0,o1,o2,o3;
        unpack2(oacc0, o0, o1);
        unpack2(oacc1, o2, o3);
        float4 ov = {o0, o1, o2, o3};
        *(float4*)(g_opart + (size_t)blockIdx.x*(B*DV) + b_o*DV + vg*4) = ov;
    }
}

// ---------------------------------------------------------------------------
// K3: outputs[b,u,v] = sum over 8 octant-partials (fixed order: deterministic)
// ---------------------------------------------------------------------------
__global__ __launch_bounds__(256) void k3_reduce(float* __restrict__ out)
{
    int e = blockIdx.x*256 + threadIdx.x;       // e over [U * B*DV)
    int u = e >> 10;
    int r = e & 1023;                            // b*32 + v
    int b = r >> 5;
    int v = r & 31;
    const float* p = g_opart + (size_t)(u*8)*(B*DV) + r;
    float s = ((p[0] + p[B*DV]) + (p[2*B*DV] + p[3*B*DV]))
            + ((p[4*B*DV] + p[5*B*DV]) + (p[6*B*DV] + p[7*B*DV]));
    out[(size_t)b*U*DV + (size_t)u*DV + v] = s;
}

// ---------------------------------------------------------------------------
extern "C" void kernel_launch(void* const* d_in, const int* in_sizes, int n_in,
                              void* d_out, int out_size)
{
    const float* att  = (const float*)d_in[0];         // attention [B,U,DK]
    const float* val  = (const float*)d_in[1];         // value     [B,U,DV]
    const float* rew  = (const float*)d_in[2];         // reward    [B]
    const void*  mask = d_in[3];                       // mask      [B,U,C] (dtype sniffed)
    const float* Watt = (const float*)d_in[4];         // W_att     [U,DK,DK]
    const float* temp = (const float*)d_in[5];         // temperature [U]
    const float* kmem = (const float*)d_in[6];         // key_mem   [U,C,DK]
    const float* vmem = (const float*)d_in[7];         // value_mem [U,C,DV]
    const float* rmem = (const float*)d_in[8];         // reward_mem [U,C]
    float* out = (float*)d_out;

    k_detect<<<1, 32>>>((const unsigned int*)mask);
    k0_query<<<U, 256>>>(att, Watt, temp);
    k1_logits<<<U*4, 256>>>(kmem, mask, rmem, out + OUT_W);
    k2_finalize<<<U*8, 256>>>(val, rew, kmem, vmem, rmem, out);
    k3_reduce<<<(U*B*DV)/256, 256>>>(out);
}

// round 8
// speedup vs baseline: 1.4249x; 1.4249x over previous
#include <cuda_runtime.h>

#define B 32
#define U 512
#define C 4096
#define DK 32
#define DV 32
#define UC (U*C)
#define MEM_RATE 0.01f
#define RWD_RATE 0.01f

// output layout: outputs[B,U,DV] | w[B,U,C] | key_new[U,C,DK] | value_new[U,C,DV] | reward_new[U,C]
#define OUT_W    524288
#define OUT_KEY  67633152
#define OUT_VAL  134742016
#define OUT_RWD  201850880

typedef unsigned long long u64;

__device__ __forceinline__ u64 pack2(float lo, float hi){
    u64 r; asm("mov.b64 %0, {%1,%2};" : "=l"(r) : "f"(lo), "f"(hi)); return r;
}
__device__ __forceinline__ void unpack2(u64 v, float& lo, float& hi){
    asm("mov.b64 {%0,%1}, %2;" : "=f"(lo), "=f"(hi) : "l"(v));
}
__device__ __forceinline__ void fma2(u64& d, u64 a, u64 b_){
    asm("fma.rn.f32x2 %0, %1, %2, %0;" : "+l"(d) : "l"(a), "l"(b_));
}
__device__ __forceinline__ void add2(u64& d, u64 a){
    asm("add.rn.f32x2 %0, %0, %1;" : "+l"(d) : "l"(a));
}

// scratch (static __device__ per harness rules)
__device__ float g_q_kb[U*DK*B];     // [u][k][b], pre-scaled by 1/temperature[u]  (for K1)
__device__ float g_q_bk[U*B*DK];     // [u][b][k], unscaled                        (for K2 refresh)
__device__ float g_denpart[U*2*B];   // per-(u,half) partial denominators
__device__ float g_opart[U*4*B*DV];  // per-(u,quarter) output partials [B][DV]
__device__ int   g_mask_mode;        // 0 = uint8, 1 = float32, 2 = int32

// ---------------------------------------------------------------------------
// K_detect: sniff the mask dtype from its bit patterns (1 warp).
// ---------------------------------------------------------------------------
__global__ void k_detect(const unsigned int* __restrict__ m)
{
    int t = threadIdx.x;
    int f32 = 0, big = 0;
    for (int i = t; i < 2048; i += 32){
        unsigned int v = m[i];
        f32 |= (v == 0x3F800000u);
        big |= (v > 1u && v != 0x3F800000u);
    }
    f32 = __any_sync(0xffffffffu, f32);
    big = __any_sync(0xffffffffu, big);
    if (t == 0) g_mask_mode = f32 ? 1 : (big ? 0 : 2);
}

// ---------------------------------------------------------------------------
// K0: query[b,u,k] = sum_d attention[b,u,d] * W_att[u,d,k]
// ---------------------------------------------------------------------------
__global__ __launch_bounds__(256) void k0_query(const float* __restrict__ att,
                                                const float* __restrict__ Watt,
                                                const float* __restrict__ temp)
{
    __shared__ float W_s[DK][DK];
    __shared__ float a_s[B][DK+1];
    const int u = blockIdx.x, t = threadIdx.x;

    for (int j = t; j < DK*DK; j += 256) W_s[j/DK][j%DK] = Watt[u*DK*DK + j];
    for (int j = t; j < B*DK; j += 256){
        int b = j/DK, d = j%DK;
        a_s[b][d] = att[(b*U + u)*DK + d];
    }
    __syncthreads();
    const float invT = 1.0f / temp[u];
    for (int j = t; j < B*DK; j += 256){
        int b = j/DK, k = j%DK;
        float s = 0.f;
        #pragma unroll
        for (int d = 0; d < DK; d++) s += a_s[b][d] * W_s[d][k];
        g_q_bk[u*B*DK + b*DK + k] = s;
        g_q_kb[u*DK*B + k*B + b] = s * invT;
    }
}

// ---------------------------------------------------------------------------
// K1: per (u, half-of-C): n[b,c] = exp(key.q)*rmem*mask -> w region;
//     partial per-b denominators -> g_denpart
// ---------------------------------------------------------------------------
__global__ __launch_bounds__(256) void k1_logits(const float* __restrict__ key_mem,
                                                 const void* __restrict__ mask,
                                                 const float* __restrict__ rmem,
                                                 float* __restrict__ w_out)   // base of w region
{
    const int u = blockIdx.x >> 1;
    const int h = blockIdx.x & 1;
    const int t = threadIdx.x;
    __shared__ __align__(16) float q_s[DK*B];        // [k][b], scaled
    __shared__ float key_s[DK*257 + 32];             // key tile transposed [k][c]; reused for reduction
    __shared__ float p2[B][8];

    for (int j = t; j < DK*B; j += 256) q_s[j] = g_q_kb[u*DK*B + j];

    const int mode = g_mask_mode;
    const unsigned char* __restrict__ mp8 = (const unsigned char*)mask + (size_t)u*C;
    const float*         __restrict__ mpf = (const float*)mask         + (size_t)u*C;
    const int*           __restrict__ mpi = (const int*)mask           + (size_t)u*C;

    const float* __restrict__ rmemu = rmem + u*C;
    float* __restrict__ nbase = w_out + u*C;

    u64 dpart2[16];
    #pragma unroll
    for (int i = 0; i < 16; i++) dpart2[i] = 0ull;

    for (int tile = h*8; tile < h*8 + 8; ++tile){
        const int c0 = tile * 256;
        __syncthreads();
        // stage key tile [256 c][32 k] transposed into key_s[k][c] (conflict-free)
        {
            const float4* __restrict__ gk =
                (const float4*)(key_mem + (size_t)u*C*DK + (size_t)c0*DK);
            #pragma unroll
            for (int j = 0; j < 8; j++){
                int f = t + j*256;
                float4 v = gk[f];
                int c = f >> 3, db = (f & 7) * 4;
                key_s[(db+0)*257 + c] = v.x;
                key_s[(db+1)*257 + c] = v.y;
                key_s[(db+2)*257 + c] = v.z;
                key_s[(db+3)*257 + c] = v.w;
            }
        }
        __syncthreads();

        const int c = c0 + t;
        u64 acc2[16];
        #pragma unroll
        for (int i = 0; i < 16; i++) acc2[i] = 0ull;

        #pragma unroll 8
        for (int k = 0; k < DK; k++){
            float kd = key_s[k*257 + t];
            u64 kd2 = pack2(kd, kd);
            const ulonglong2* __restrict__ qp = (const ulonglong2*)(&q_s[k*B]);
            #pragma unroll
            for (int j = 0; j < 8; j++){
                ulonglong2 p = qp[j];
                fma2(acc2[2*j],   kd2, p.x);
                fma2(acc2[2*j+1], kd2, p.y);
            }
        }

        const float rm = rmemu[c];
        float* __restrict__ np = nbase + c;
        #pragma unroll
        for (int i = 0; i < 16; i++){
            float l0, l1; unpack2(acc2[i], l0, l1);
            float e0 = __expf(l0) * rm;
            float e1 = __expf(l1) * rm;
            int b0 = 2*i, b1 = 2*i + 1;
            size_t i0 = (size_t)b0*UC + c;
            size_t i1 = (size_t)b1*UC + c;
            bool keep0, keep1;
            if (mode == 0)      { keep0 = mp8[i0] != 0;   keep1 = mp8[i1] != 0;   }
            else if (mode == 1) { keep0 = mpf[i0] != 0.f; keep1 = mpf[i1] != 0.f; }
            else                { keep0 = mpi[i0] != 0;   keep1 = mpi[i1] != 0;   }
            float n0 = keep0 ? e0 : 0.f;
            float n1 = keep1 ? e1 : 0.f;
            np[(size_t)b0*UC] = n0;
            np[(size_t)b1*UC] = n1;
            add2(dpart2[i], pack2(n0, n1));
        }
    }

    // deterministic partial-denominator reduction (reuse key_s as [b][256] scratch)
    __syncthreads();
    #pragma unroll
    for (int i = 0; i < 16; i++){
        float d0, d1; unpack2(dpart2[i], d0, d1);
        key_s[(2*i)*256 + t]   = d0;
        key_s[(2*i+1)*256 + t] = d1;
    }
    __syncthreads();
    {
        int b = t >> 3, seg = t & 7;
        float s = 0.f;
        #pragma unroll
        for (int j = 0; j < 32; j++) s += key_s[b*256 + seg*32 + j];
        p2[b][seg] = s;
    }
    __syncthreads();
    if (t < B){
        float s = 0.f;
        #pragma unroll
        for (int j = 0; j < 8; j++) s += p2[t][j];
        g_denpart[(u*2 + h)*B + t] = s;
    }
}

// ---------------------------------------------------------------------------
// K2: per (u, quarter-of-C), software-pipelined: prefetch next tile's n + vm
//     during current tile's compute. invden from partials, finalize w, retain,
//     key/value/reward refresh, partial outputs -> g_opart
// ---------------------------------------------------------------------------
__global__ __launch_bounds__(256, 2) void k2_finalize(const float* __restrict__ valin,
                                                      const float* __restrict__ reward,
                                                      const float* __restrict__ key_mem,
                                                      const float* __restrict__ value_mem,
                                                      const float* __restrict__ rmem,
                                                      float* __restrict__ out)
{
    const int u  = blockIdx.x >> 2;
    const int q4 = blockIdx.x & 3;
    const int t  = threadIdx.x;
    __shared__ __align__(16) float w_s[B][128];
    __shared__ __align__(16) float vm_s[128][DV];
    __shared__ __align__(16) float q_s[B][DK];
    __shared__ __align__(16) float v_s[B][DV];
    __shared__ float S_s[128];
    __shared__ float Spart[2][128];
    __shared__ float invden_s[B], rw_s[B];

    for (int j = t; j < B*DK; j += 256) q_s[j/DK][j%DK] = g_q_bk[u*B*DK + j];
    for (int j = t; j < B*DV; j += 256){
        int b = j/DV, v = j%DV;
        v_s[b][v] = valin[(b*U + u)*DV + v];
    }
    if (t < B){
        const float* dp = g_denpart + (size_t)(u*2)*B + t;
        invden_s[t] = 1.0f / (dp[0] + dp[B]);
        rw_s[t] = reward[t];
    }

    float* __restrict__ w_out   = out + OUT_W   + (size_t)u*C;
    float* __restrict__ key_out = out + OUT_KEY + (size_t)u*C*DK;
    float* __restrict__ val_out = out + OUT_VAL + (size_t)u*C*DV;
    float* __restrict__ rwd_out = out + OUT_RWD + (size_t)u*C;
    const float* __restrict__ km    = key_mem   + (size_t)u*C*DK;
    const float* __restrict__ vm    = value_mem + (size_t)u*C*DV;
    const float* __restrict__ rmemu = rmem      + (size_t)u*C;

    const int half = t >> 7;     // Phase A: which half of b
    const int cA   = t & 127;    // Phase A: c within tile
    const int b_o  = t >> 3;     // outputs accumulator: batch row
    const int vg   = t & 7;      // outputs accumulator: 4-wide v group
    u64 oacc0 = 0ull, oacc1 = 0ull;

    // prefetch tile 0 of this quarter
    float  n_pre[16];
    float4 vm_pre[4];
    {
        const int c0 = q4*8*128;
        #pragma unroll
        for (int j = 0; j < 16; j++){
            int b = half*16 + j;
            n_pre[j] = w_out[b*UC + c0 + cA];
        }
        const float4* __restrict__ src = (const float4*)(vm + (size_t)c0*DV);
        #pragma unroll
        for (int j = 0; j < 4; j++) vm_pre[j] = src[t + j*256];
    }
    __syncthreads();

    for (int it = 0; it < 8; ++it){
        const int c0 = (q4*8 + it) * 128;

        // Phase A: finalize w from prefetched n, stage w_s + vm_s, column sums
        {
            float sacc = 0.f;
            #pragma unroll
            for (int j = 0; j < 16; j++){
                int b = half*16 + j;
                float w = n_pre[j] * invden_s[b];
                w_out[b*UC + c0 + cA] = w;
                w_s[b][cA] = w;
                sacc += w;
            }
            Spart[half][cA] = sacc;
            float4* __restrict__ dst = (float4*)(&vm_s[0][0]);
            #pragma unroll
            for (int j = 0; j < 4; j++) dst[t + j*256] = vm_pre[j];
        }
        __syncthreads();
        if (t < 128) S_s[t] = Spart[0][t] + Spart[1][t];

        // prefetch next tile (LDGs issued here, consumed next iteration —
        // Phase B/C compute below hides the DRAM latency)
        if (it < 7){
            const int c0n = c0 + 128;
            #pragma unroll
            for (int j = 0; j < 16; j++){
                int b = half*16 + j;
                n_pre[j] = w_out[b*UC + c0n + cA];
            }
            const float4* __restrict__ src = (const float4*)(vm + (size_t)c0n*DV);
            #pragma unroll
            for (int j = 0; j < 4; j++) vm_pre[j] = src[t + j*256];
        }
        __syncthreads();

        // Phase B: key/value refresh GEMMs  [128c x 32k], K = 32 batches
        {
            const int kg = t & 7;       // k = kg*4 .. +3
            const int cg = t >> 3;      // c_local = cg*4 .. +3
            u64 kacc[4][2], vacc[4][2];
            #pragma unroll
            for (int i = 0; i < 4; i++){
                kacc[i][0]=0ull; kacc[i][1]=0ull; vacc[i][0]=0ull; vacc[i][1]=0ull;
            }
            #pragma unroll 8
            for (int b = 0; b < B; b++){
                float4 w4 = *(const float4*)(&w_s[b][cg*4]);
                ulonglong2 q2 = *(const ulonglong2*)(&q_s[b][kg*4]);
                ulonglong2 v2 = *(const ulonglong2*)(&v_s[b][kg*4]);
                float wa[4] = {w4.x, w4.y, w4.z, w4.w};
                #pragma unroll
                for (int i = 0; i < 4; i++){
                    u64 wp = pack2(wa[i], wa[i]);
                    fma2(kacc[i][0], wp, q2.x);
                    fma2(kacc[i][1], wp, q2.y);
                    fma2(vacc[i][0], wp, v2.x);
                    fma2(vacc[i][1], wp, v2.y);
                }
            }
            #pragma unroll
            for (int i = 0; i < 4; i++){
                int cl = cg*4 + i;
                int c  = c0 + cl;
                float retain = 1.0f - MEM_RATE * S_s[cl];
                float a0,a1,a2,a3;
                unpack2(kacc[i][0], a0, a1); unpack2(kacc[i][1], a2, a3);
                float4 kmv = *(const float4*)(km + (size_t)c*DK + kg*4);
                float4 r;
                r.x = kmv.x*retain + MEM_RATE*a0;
                r.y = kmv.y*retain + MEM_RATE*a1;
                r.z = kmv.z*retain + MEM_RATE*a2;
                r.w = kmv.w*retain + MEM_RATE*a3;
                *(float4*)(key_out + (size_t)c*DK + kg*4) = r;

                unpack2(vacc[i][0], a0, a1); unpack2(vacc[i][1], a2, a3);
                float4 vmv = *(const float4*)(&vm_s[cl][kg*4]);
                float4 r2;
                r2.x = vmv.x*retain + MEM_RATE*a0;
                r2.y = vmv.y*retain + MEM_RATE*a1;
                r2.z = vmv.z*retain + MEM_RATE*a2;
                r2.w = vmv.w*retain + MEM_RATE*a3;
                *(float4*)(val_out + (size_t)c*DV + kg*4) = r2;
            }
        }

        // reward refresh
        if (t < 128){
            int c = t;
            float racc = 0.f;
            #pragma unroll
            for (int b = 0; b < B; b++) racc += w_s[b][c] * rw_s[b];
            float retain = 1.0f - RWD_RATE * S_s[c];
            rwd_out[c0 + c] = rmemu[c0 + c] * retain + RWD_RATE * racc;
        }

        // Phase C: outputs accumulation  o[b][v] += sum_c w[b][c]*value_mem[c][v]
        {
            #pragma unroll 8
            for (int c = 0; c < 128; c++){
                float w = w_s[b_o][c];
                u64 wp = pack2(w, w);
                ulonglong2 vv = *(const ulonglong2*)(&vm_s[c][vg*4]);
                fma2(oacc0, wp, vv.x);
                fma2(oacc1, wp, vv.y);
            }
        }
        __syncthreads();
    }

    // write output partials [CTA][B][DV]
    {
        float o0,o1,o2,o3;
        unpack2(oacc0, o0, o1);
        unpack2(oacc1, o2, o3);
        float4 ov = {o0, o1, o2, o3};
        *(float4*)(g_opart + (size_t)blockIdx.x*(B*DV) + b_o*DV + vg*4) = ov;
    }
}

// ---------------------------------------------------------------------------
// K3: outputs[b,u,v] = sum over 4 quarter-partials (fixed order: deterministic)
// ---------------------------------------------------------------------------
__global__ __launch_bounds__(256) void k3_reduce(float* __restrict__ out)
{
    int e = blockIdx.x*256 + threadIdx.x;       // e over [U * B*DV)
    int u = e >> 10;
    int r = e & 1023;                            // b*32 + v
    int b = r >> 5;
    int v = r & 31;
    const float* p = g_opart + (size_t)(u*4)*(B*DV) + r;
    float s = (p[0] + p[B*DV]) + (p[2*B*DV] + p[3*B*DV]);
    out[(size_t)b*U*DV + (size_t)u*DV + v] = s;
}

// ---------------------------------------------------------------------------
extern "C" void kernel_launch(void* const* d_in, const int* in_sizes, int n_in,
                              void* d_out, int out_size)
{
    const float* att  = (const float*)d_in[0];         // attention [B,U,DK]
    const float* val  = (const float*)d_in[1];         // value     [B,U,DV]
    const float* rew  = (const float*)d_in[2];         // reward    [B]
    const void*  mask = d_in[3];                       // mask      [B,U,C] (dtype sniffed)
    const float* Watt = (const float*)d_in[4];         // W_att     [U,DK,DK]
    const float* temp = (const float*)d_in[5];         // temperature [U]
    const float* kmem = (const float*)d_in[6];         // key_mem   [U,C,DK]
    const float* vmem = (const float*)d_in[7];         // value_mem [U,C,DV]
    const float* rmem = (const float*)d_in[8];         // reward_mem [U,C]
    float* out = (float*)d_out;

    k_detect<<<1, 32>>>((const unsigned int*)mask);
    k0_query<<<U, 256>>>(att, Watt, temp);
    k1_logits<<<U*2, 256>>>(kmem, mask, rmem, out + OUT_W);
    k2_finalize<<<U*4, 256>>>(val, rew, kmem, vmem, rmem, out);
    k3_reduce<<<(U*B*DV)/256, 256>>>(out);
}